// round 15
// baseline (speedup 1.0000x reference)
#include <cuda_runtime.h>
#include <cuda_fp16.h>

// Problem constants (fixed shapes for this problem instance)
#define NN 100000   // nodes
#define NE 800000   // edges
#define VC 256      // vocab
#define DM 256      // node dim == hidden == vocab
#define NM 10000    // masked outputs

#define SB 512
#define NSB ((NN + SB - 1) / SB)   // 196 scan blocks
#define NW2B 128                   // W2 cvt blocks (65536 elems / 512)

// ---------------- scratch (device globals; no allocation allowed) ----------
// g_dmn = [deg | masked | needed], zeroed by ONE cudaMemsetAsync (no k_init).
// deg counts EDGES into node (self loop handled as +1 at dinv; trip count = deg).
__device__ int   g_dmn[3 * NN];
#define DEG(i)    g_dmn[(i)]
#define MASKED(i) g_dmn[NN + (i)]
#define NEEDED(i) g_dmn[2 * NN + (i)]
__device__ int   g_cur[NN];     // seeded to off | masked<<31 in scanBC
__device__ int   g_off[NN];
__device__ int   g_bsum[NSB];
__device__ float g_dinv[NN];
__device__ __align__(8)  int2   g_nv[NN];          // {x, dinv_bits}
__device__ __align__(16) __half g_EWh[VC * DM];    // emb @ W1, fp16 (128 KB)
__device__ __align__(16) __half g_W2p[DM * VC];    // W2 fp16, k-quad packed (128 KB)
__device__ __align__(16) __half g_out1h[NN * DM];  // relu(layer-1), fp16 (51 MB)
__device__ __align__(16) int4   g_edge[NE];        // {x[src], src, dinv_s_bits, 0}

// ---------------- kernels ---------------------------------------------------

// degree count (first NE threads) + mask marking (next NM)
__global__ void k_degmark(const int* __restrict__ ei, const int* __restrict__ mask) {
    int t = blockIdx.x * blockDim.x + threadIdx.x;
    if (t < NE) {
        atomicAdd(&DEG(ei[NE + t]), 1);
    } else if (t < NE + NM) {
        int n = mask[t - NE];
        MASKED(n) = 1;
        NEEDED(n) = 1;            // self term of layer-2 reads out1[node]
    }
}

// blocks [0,NSB): scanA | [NSB,NSB+VC): EW row | [NSB+VC,NSB+VC+NW2B): W2 cvt
__global__ void k_scanAew(const float* __restrict__ emb, const float* __restrict__ W1,
                          const float* __restrict__ W2) {
    __shared__ float sf[SB];
    if (blockIdx.x < NSB) {
        // ---- scanA: per-block exclusive scan of deg (edge counts) ----
        int* s = reinterpret_cast<int*>(sf);
        int i = blockIdx.x * SB + threadIdx.x;
        int v = (i < NN) ? DEG(i) : 0;
        s[threadIdx.x] = v;
        __syncthreads();
        for (int o = 1; o < SB; o <<= 1) {
            int t = (threadIdx.x >= o) ? s[threadIdx.x - o] : 0;
            __syncthreads();
            s[threadIdx.x] += t;
            __syncthreads();
        }
        int inc = s[threadIdx.x];
        if (i < NN) g_off[i] = inc - v;             // exclusive (pre-bsum)
        if (threadIdx.x == SB - 1) g_bsum[blockIdx.x] = inc;
    } else if (blockIdx.x < NSB + VC) {
        // ---- EW row: g_EWh[r] = fp16(emb[r] @ W1) ----
        int r = blockIdx.x - NSB;
        int c = threadIdx.x;
        if (c < DM) sf[c] = emb[r * DM + c];
        __syncthreads();
        if (c >= DM) return;
        float acc = 0.f;
#pragma unroll 8
        for (int k = 0; k < DM; k++) acc += sf[k] * W1[k * DM + c];
        g_EWh[r * DM + c] = __float2half(acc);
    } else {
        // ---- W2 cvt + k-quad pack: W2p[(kk*256+c)*4+i] = fp16(W2[(4kk+i)*256+c])
        int o = (blockIdx.x - NSB - VC) * SB + threadIdx.x;   // 0..65535
        int i = o & 3;
        int c = (o >> 2) & (DM - 1);
        int kk = o >> 10;
        g_W2p[o] = __float2half(W2[(4 * kk + i) * DM + c]);
    }
}

// fused scanB+scanC+dinv; seeds g_cur = off | masked<<31; builds node record
__global__ void k_scanBC(const int* __restrict__ x) {
    __shared__ int s[256];
    int t = threadIdx.x;
    if (t < 256) {
        int v = (t < NSB) ? g_bsum[t] : 0;
        s[t] = v;
    }
    __syncthreads();
    for (int o = 1; o < 256; o <<= 1) {
        int u = 0;
        if (t < 256 && t >= o) u = s[t - o];
        __syncthreads();
        if (t < 256) s[t] += u;
        __syncthreads();
    }
    int pre = (blockIdx.x == 0) ? 0 : s[blockIdx.x - 1];
    int i = blockIdx.x * SB + t;
    if (i < NN) {
        int off = g_off[i] + pre;
        g_off[i] = off;
        g_cur[i] = off | (MASKED(i) << 31);         // atomic return carries flag
        float di = rsqrtf((float)(DEG(i) + 1));     // +1 = self loop
        g_dinv[i] = di;
        g_nv[i] = make_int2(x[i], __float_as_int(di));
    }
}

// place edges into CSR slots. 3 scattered ops/edge: nv[s] read, atomic
// (slot + masked flag in bit31), 16B record store (int4 -> decode-free gathers).
__global__ void k_place(const int* __restrict__ ei) {
    int e = blockIdx.x * blockDim.x + threadIdx.x;
    if (e >= NE) return;
    int s = ei[e];
    int d = ei[NE + e];
    int2 nvs = g_nv[s];                             // {x[s], dinv_s}
    int old = atomicAdd(&g_cur[d], 1);
    int slot = old & 0x7fffffff;
    g_edge[slot] = make_int4(nvs.x, s, nvs.y, 0);
    if (old < 0) NEEDED(s) = 1;                     // dst is masked
}

// layer-1 gather: out1h[i] = fp16(relu(b1 + di*(di*EW[x[i]] + sum ds*EW[x_s])))
// 64 threads/node; EW fp16 (L1-resident); R11-proven inner loop shape.
__global__ void k_gather1(const int* __restrict__ x, const float* __restrict__ b1) {
    int node = blockIdx.x * 4 + (threadIdx.x >> 6);
    if (node >= NN) return;
    if (!NEEDED(node)) return;                      // uniform per 64-thread group
    int q = threadIdx.x & 63;

    const uint2* EW2 = reinterpret_cast<const uint2*>(g_EWh);  // 4 halves/thread
    float di = g_dinv[node];

    uint2 w0u = EW2[x[node] * 64 + q];
    float2 f0a = __half22float2(*reinterpret_cast<__half2*>(&w0u.x));
    float2 f0b = __half22float2(*reinterpret_cast<__half2*>(&w0u.y));
    float4 acc = make_float4(di * f0a.x, di * f0a.y, di * f0b.x, di * f0b.y);

    int k   = g_off[node];
    int end = k + DEG(node);
    for (; k < end; k++) {
        int4 rec = g_edge[k];                       // broadcast LDG.128
        float ds = __int_as_float(rec.z);
        uint2 wu = EW2[rec.x * 64 + q];             // L1 hit (128 KB working set)
        float2 fa = __half22float2(*reinterpret_cast<__half2*>(&wu.x));
        float2 fb = __half22float2(*reinterpret_cast<__half2*>(&wu.y));
        acc.x += ds * fa.x; acc.y += ds * fa.y;
        acc.z += ds * fb.x; acc.w += ds * fb.y;
    }
    float4 bb = reinterpret_cast<const float4*>(b1)[q];
    float4 res = make_float4(bb.x + di * acc.x, bb.y + di * acc.y,
                             bb.z + di * acc.z, bb.w + di * acc.w);

    // store relu(res) fp16 — layer 2 only ever consumes relu(out1)
    __half2 oa = __floats2half2_rn(fmaxf(res.x, 0.f), fmaxf(res.y, 0.f));
    __half2 ob = __floats2half2_rn(fmaxf(res.z, 0.f), fmaxf(res.w, 0.f));
    uint2 ou;
    ou.x = *reinterpret_cast<unsigned*>(&oa);
    ou.y = *reinterpret_cast<unsigned*>(&ob);
    reinterpret_cast<uint2*>(g_out1h)[node * 64 + q] = ou;
}

// FUSED layer-2 gather + final GEMM + log-softmax. One block per 16 output rows.
// Phase 1 (gather2): 256 threads = 4 node-groups of 64; each group runs the
// proven gather2 loop for its node and writes the row directly into smem A.
// Phase 2 (final): untouched FFMA2 GEMM vs L1-resident packed fp16 W2 + softmax.
// Deletes: gather2 launch, 10MB g_aggc round-trip.
#define FROWS 16
__global__ void k_final(const int* __restrict__ mask, const float* __restrict__ b2,
                        float* __restrict__ out) {
    __shared__ float A[FROWS * DM];
    __shared__ float red[8];
    int c  = threadIdx.x;
    int j0 = blockIdx.x * FROWS;

    // ---- phase 1: gather2 into smem A ----
    {
        int sub = c >> 6;                           // 0..3 node-group in wave
        int q   = c & 63;
        const uint2* O2 = reinterpret_cast<const uint2*>(g_out1h);
#pragma unroll 1
        for (int rr = 0; rr < FROWS; rr += 4) {
            int r = rr + sub;
            int node = mask[j0 + r];
            float di = g_dinv[node];

            uint2 hu = O2[node * 64 + q];
            float2 ha = __half22float2(*reinterpret_cast<__half2*>(&hu.x));
            float2 hb = __half22float2(*reinterpret_cast<__half2*>(&hu.y));
            float4 acc = make_float4(di * ha.x, di * ha.y, di * hb.x, di * hb.y);

            int k   = g_off[node];
            int end = k + DEG(node);
            for (; k < end; k++) {
                int4 rec = g_edge[k];               // broadcast LDG.128
                float ds = __int_as_float(rec.z);
                uint2 su = O2[rec.y * 64 + q];      // 512B scattered row
                float2 sa = __half22float2(*reinterpret_cast<__half2*>(&su.x));
                float2 sb = __half22float2(*reinterpret_cast<__half2*>(&su.y));
                acc.x += ds * sa.x; acc.y += ds * sa.y;
                acc.z += ds * sb.x; acc.w += ds * sb.y;
            }
            reinterpret_cast<float4*>(A)[r * (DM / 4) + q] =
                make_float4(di * acc.x, di * acc.y, di * acc.z, di * acc.w);
        }
    }
    __syncthreads();

    // ---- phase 2: GEMM + log-softmax (proven FFMA2 loop, unchanged) ----
    float bc = b2[c];
    unsigned long long acc2[FROWS];
    unsigned long long bcpk;
    asm("mov.b64 %0, {%1, %2};" : "=l"(bcpk) : "f"(bc), "f"(0.f));
#pragma unroll
    for (int r = 0; r < FROWS; r++) acc2[r] = bcpk;

    const ulonglong2* A8 = reinterpret_cast<const ulonglong2*>(A);  // {f0,f1},{f2,f3}
    const uint2* W2p2 = reinterpret_cast<const uint2*>(g_W2p);
#pragma unroll 4
    for (int kk = 0; kk < DM / 4; kk++) {
        uint2 wu = W2p2[kk * DM + c];               // 4 halves: k=4kk..4kk+3, col c
        float2 w01 = __half22float2(*reinterpret_cast<__half2*>(&wu.x));
        float2 w23 = __half22float2(*reinterpret_cast<__half2*>(&wu.y));
        unsigned long long wp01, wp23;
        asm("mov.b64 %0, {%1, %2};" : "=l"(wp01) : "f"(w01.x), "f"(w01.y));
        asm("mov.b64 %0, {%1, %2};" : "=l"(wp23) : "f"(w23.x), "f"(w23.y));
#pragma unroll
        for (int r = 0; r < FROWS; r++) {
            ulonglong2 av = A8[r * (DM / 4) + kk];  // LDS.128 broadcast
            asm("fma.rn.f32x2 %0, %1, %2, %0;" : "+l"(acc2[r]) : "l"(av.x), "l"(wp01));
            asm("fma.rn.f32x2 %0, %1, %2, %0;" : "+l"(acc2[r]) : "l"(av.y), "l"(wp23));
        }
    }

    float acc[FROWS];
#pragma unroll
    for (int r = 0; r < FROWS; r++) {
        float lo, hi;
        asm("mov.b64 {%0, %1}, %2;" : "=f"(lo), "=f"(hi) : "l"(acc2[r]));
        acc[r] = lo + hi;
    }

    int lane = c & 31, wid = c >> 5;
#pragma unroll 1
    for (int r = 0; r < FROWS; r++) {
        float v = acc[r];
#pragma unroll
        for (int o = 16; o; o >>= 1) v = fmaxf(v, __shfl_xor_sync(0xffffffffu, v, o));
        if (lane == 0) red[wid] = v;
        __syncthreads();
        float m = red[0];
#pragma unroll
        for (int w = 1; w < 8; w++) m = fmaxf(m, red[w]);
        __syncthreads();
        float s = __expf(acc[r] - m);
#pragma unroll
        for (int o = 16; o; o >>= 1) s += __shfl_xor_sync(0xffffffffu, s, o);
        if (lane == 0) red[wid] = s;
        __syncthreads();
        float tot = red[0];
#pragma unroll
        for (int w = 1; w < 8; w++) tot += red[w];
        __syncthreads();
        out[(j0 + r) * DM + c] = acc[r] - m - logf(tot);
    }
}

// ---------------- launch -----------------------------------------------------
extern "C" void kernel_launch(void* const* d_in, const int* in_sizes, int n_in,
                              void* d_out, int out_size) {
    const int*   x    = (const int*)d_in[0];   // (100000,1) int32
    const int*   ei   = (const int*)d_in[1];   // (2,800000) int32: [src | dst]
    const int*   mask = (const int*)d_in[2];   // (10000,)   int32
    const float* emb  = (const float*)d_in[3]; // (256,256)
    const float* W1   = (const float*)d_in[4]; // (256,256)
    const float* b1   = (const float*)d_in[5]; // (256,)
    const float* W2   = (const float*)d_in[6]; // (256,256)
    const float* b2   = (const float*)d_in[7]; // (256,)
    float* out = (float*)d_out;                // (10000,256)

    (void)in_sizes; (void)n_in; (void)out_size;

    // zero deg|masked|needed in one memset node (replaces k_init kernel)
    void* dmn_ptr = nullptr;
    cudaGetSymbolAddress(&dmn_ptr, g_dmn);
    cudaMemsetAsync(dmn_ptr, 0, sizeof(int) * 3 * NN);

    k_degmark<<<(NE + NM + 255) / 256, 256>>>(ei, mask);
    k_scanAew<<<NSB + VC + NW2B, SB>>>(emb, W1, W2);
    k_scanBC <<<NSB, SB>>>(x);
    k_place  <<<(NE + 255) / 256, 256>>>(ei);
    k_gather1<<<(NN + 3) / 4, 256>>>(x, b1);
    k_final  <<<NM / FROWS, DM>>>(mask, b2, out);   // fused gather2 + GEMM
}

// round 16
// speedup vs baseline: 1.0341x; 1.0341x over previous
#include <cuda_runtime.h>
#include <cuda_fp16.h>

// Problem constants (fixed shapes for this problem instance)
#define NN 100000   // nodes
#define NE 800000   // edges
#define VC 256      // vocab
#define DM 256      // node dim == hidden == vocab
#define NM 10000    // masked outputs

#define SB 512
#define NSB ((NN + SB - 1) / SB)   // 196 scan blocks
#define NW2B 128                   // W2 cvt blocks (65536 elems / 512)

// ---------------- scratch (device globals; no allocation allowed) ----------
__device__ int   g_deg[NN];
__device__ int   g_cur[NN];     // seeded to off | masked<<31 in scan epilogue
__device__ int   g_off[NN];
__device__ int   g_masked[NN];
__device__ int   g_needed[NN];
__device__ float g_dinv[NN];
__device__ unsigned long long g_state[NSB];        // lookback: flag<<62 | value
__device__ __align__(8)  int2   g_nv[NN];          // {x, dinv_bits}
__device__ __align__(16) __half g_EWh[VC * DM];    // emb @ W1, fp16 (128 KB)
__device__ __align__(16) __half g_W2p[DM * VC];    // W2 fp16, k-quad packed (128 KB)
__device__ __align__(16) __half g_out1h[NN * DM];  // relu(layer-1), fp16 (51 MB)
__device__ __align__(16) float  g_aggc[NM * DM];   // layer-2 aggregate (10 MB)
__device__ __align__(16) int4   g_edge[NE];        // {x[src], src, dinv_s_bits, 0}

// ---------------- kernels ---------------------------------------------------
__global__ void k_init(void) {
    int i = blockIdx.x * blockDim.x + threadIdx.x;
    if (i < NN) { g_deg[i] = 1; g_masked[i] = 0; g_needed[i] = 0; }
    if (i < NSB) g_state[i] = 0ULL;                 // reset lookback states
}

// degree count (first NE threads) + mask marking (next NM)
__global__ void k_degmark(const int* __restrict__ ei, const int* __restrict__ mask) {
    int t = blockIdx.x * blockDim.x + threadIdx.x;
    if (t < NE) {
        atomicAdd(&g_deg[ei[NE + t]], 1);
    } else if (t < NE + NM) {
        int n = mask[t - NE];
        g_masked[n] = 1;
        g_needed[n] = 1;          // self term of layer-2 reads out1[node]
    }
}

// ONE kernel: blocks [0,NSB) = single-pass decoupled-lookback scan of (deg-1)
// + full epilogue (off, cur|masked<<31, dinv, nv). Blocks [NSB,NSB+VC) = EW
// rows. Blocks [NSB+VC, +NW2B) = W2 fp16 k-quad pack. Replaces scanA + scanBC.
// Deadlock-safe: scan blocks are bids 0..195, all wave-1 co-resident
// (512-thread blocks, >=2 blocks/SM -> >=296 wave-1 slots > 196).
__global__ void __launch_bounds__(SB) k_scanEw(const int* __restrict__ x,
                                               const float* __restrict__ emb,
                                               const float* __restrict__ W1,
                                               const float* __restrict__ W2) {
    __shared__ float sf[SB];
    __shared__ unsigned sh_excl;
    if (blockIdx.x < NSB) {
        // ---- per-block inclusive scan of (deg-1) ----
        int* s = reinterpret_cast<int*>(sf);
        int i = blockIdx.x * SB + threadIdx.x;
        int v = (i < NN) ? (g_deg[i] - 1) : 0;
        s[threadIdx.x] = v;
        __syncthreads();
        for (int o = 1; o < SB; o <<= 1) {
            int t = (threadIdx.x >= o) ? s[threadIdx.x - o] : 0;
            __syncthreads();
            s[threadIdx.x] += t;
            __syncthreads();
        }
        int inc = s[threadIdx.x];
        int blockAgg = s[SB - 1];

        // ---- decoupled lookback (thread 0) ----
        if (threadIdx.x == 0) {
            unsigned excl = 0;
            if (blockIdx.x == 0) {
                atomicExch(&g_state[0], (2ULL << 62) | (unsigned)blockAgg);
            } else {
                atomicExch(&g_state[blockIdx.x], (1ULL << 62) | (unsigned)blockAgg);
                int j = blockIdx.x - 1;
                while (true) {
                    unsigned long long st = atomicAdd(&g_state[j], 0ULL);
                    unsigned f = (unsigned)(st >> 62);
                    if (f == 0) continue;           // spin: predecessor not ready
                    excl += (unsigned)st;
                    if (f == 2u) break;             // inclusive prefix found
                    j--;
                }
                atomicExch(&g_state[blockIdx.x],
                           (2ULL << 62) | (unsigned long long)(excl + (unsigned)blockAgg));
            }
            sh_excl = excl;
        }
        __syncthreads();

        // ---- epilogue (was scanBC): offsets, cur|flag, dinv, node record ----
        if (i < NN) {
            int off = (inc - v) + (int)sh_excl;     // exclusive global prefix
            g_off[i] = off;
            g_cur[i] = off | (g_masked[i] << 31);   // atomic return carries flag
            float di = rsqrtf((float)(v + 1));      // deg = v+1 (self loop incl)
            g_dinv[i] = di;
            g_nv[i] = make_int2(x[i], __float_as_int(di));
        }
    } else if (blockIdx.x < NSB + VC) {
        // ---- EW row: g_EWh[r] = fp16(emb[r] @ W1) ----
        int r = blockIdx.x - NSB;
        int c = threadIdx.x;
        if (c < DM) sf[c] = emb[r * DM + c];
        __syncthreads();
        if (c >= DM) return;
        float acc = 0.f;
#pragma unroll 8
        for (int k = 0; k < DM; k++) acc += sf[k] * W1[k * DM + c];
        g_EWh[r * DM + c] = __float2half(acc);
    } else {
        // ---- W2 cvt + k-quad pack: W2p[(kk*256+c)*4+i] = fp16(W2[(4kk+i)*256+c])
        int o = (blockIdx.x - NSB - VC) * SB + threadIdx.x;   // 0..65535
        int i = o & 3;
        int c = (o >> 2) & (DM - 1);
        int kk = o >> 10;
        g_W2p[o] = __float2half(W2[(4 * kk + i) * DM + c]);
    }
}

// place edges into CSR slots. 3 scattered ops/edge: nv[s] read, atomic
// (slot + masked flag in bit31), 16B record store (int4 -> decode-free gathers).
__global__ void k_place(const int* __restrict__ ei) {
    int e = blockIdx.x * blockDim.x + threadIdx.x;
    if (e >= NE) return;
    int s = ei[e];
    int d = ei[NE + e];
    int2 nvs = g_nv[s];                             // {x[s], dinv_s}
    int old = atomicAdd(&g_cur[d], 1);
    int slot = old & 0x7fffffff;
    g_edge[slot] = make_int4(nvs.x, s, nvs.y, 0);
    if (old < 0) g_needed[s] = 1;                   // dst is masked
}

// layer-1 gather: out1h[i] = fp16(relu(b1 + di*(di*EW[x[i]] + sum ds*EW[x_s])))
// 64 threads/node; EW fp16 (L1-resident); R11/R14-proven inner loop shape.
__global__ void k_gather1(const int* __restrict__ x, const float* __restrict__ b1) {
    int node = blockIdx.x * 4 + (threadIdx.x >> 6);
    if (node >= NN) return;
    if (!g_needed[node]) return;                    // uniform per 64-thread group
    int q = threadIdx.x & 63;

    const uint2* EW2 = reinterpret_cast<const uint2*>(g_EWh);  // 4 halves/thread
    float di = g_dinv[node];

    uint2 w0u = EW2[x[node] * 64 + q];
    float2 f0a = __half22float2(*reinterpret_cast<__half2*>(&w0u.x));
    float2 f0b = __half22float2(*reinterpret_cast<__half2*>(&w0u.y));
    float4 acc = make_float4(di * f0a.x, di * f0a.y, di * f0b.x, di * f0b.y);

    int k   = g_off[node];
    int end = k + g_deg[node] - 1;
    for (; k < end; k++) {
        int4 rec = g_edge[k];                       // broadcast LDG.128
        float ds = __int_as_float(rec.z);
        uint2 wu = EW2[rec.x * 64 + q];             // L1 hit (128 KB working set)
        float2 fa = __half22float2(*reinterpret_cast<__half2*>(&wu.x));
        float2 fb = __half22float2(*reinterpret_cast<__half2*>(&wu.y));
        acc.x += ds * fa.x; acc.y += ds * fa.y;
        acc.z += ds * fb.x; acc.w += ds * fb.y;
    }
    float4 bb = reinterpret_cast<const float4*>(b1)[q];
    float4 res = make_float4(bb.x + di * acc.x, bb.y + di * acc.y,
                             bb.z + di * acc.z, bb.w + di * acc.w);

    // store relu(res) fp16 — layer 2 only ever consumes relu(out1)
    __half2 oa = __floats2half2_rn(fmaxf(res.x, 0.f), fmaxf(res.y, 0.f));
    __half2 ob = __floats2half2_rn(fmaxf(res.z, 0.f), fmaxf(res.w, 0.f));
    uint2 ou;
    ou.x = *reinterpret_cast<unsigned*>(&oa);
    ou.y = *reinterpret_cast<unsigned*>(&ob);
    reinterpret_cast<uint2*>(g_out1h)[node * 64 + q] = ou;
}

// layer-2 gather, masked entries only (compact j-indexed output):
//   aggc[j] = di*(di*h1[node] + sum ds*h1[src])   (h1 already relu'd)
__global__ void k_gather2(const int* __restrict__ mask) {
    int gid = blockIdx.x * blockDim.x + threadIdx.x;
    int j = gid >> 6;
    if (j >= NM) return;
    int q = gid & 63;
    int node = mask[j];

    const uint2* O2 = reinterpret_cast<const uint2*>(g_out1h);
    float di = g_dinv[node];

    uint2 hu = O2[node * 64 + q];
    float2 ha = __half22float2(*reinterpret_cast<__half2*>(&hu.x));
    float2 hb = __half22float2(*reinterpret_cast<__half2*>(&hu.y));
    float4 acc = make_float4(di * ha.x, di * ha.y, di * hb.x, di * hb.y);

    int k   = g_off[node];
    int end = k + g_deg[node] - 1;
    for (; k < end; k++) {
        int4 rec = g_edge[k];                       // broadcast LDG.128
        float ds = __int_as_float(rec.z);
        uint2 su = O2[rec.y * 64 + q];              // 512B scattered row
        float2 sa = __half22float2(*reinterpret_cast<__half2*>(&su.x));
        float2 sb = __half22float2(*reinterpret_cast<__half2*>(&su.y));
        acc.x += ds * sa.x; acc.y += ds * sa.y;
        acc.z += ds * sb.x; acc.w += ds * sb.y;
    }
    reinterpret_cast<float4*>(g_aggc)[j * 64 + q] =
        make_float4(di * acc.x, di * acc.y, di * acc.z, di * acc.w);
}

// out[j] = log_softmax(aggc[j] @ W2 + b2); W2 fp16 k-quad packed, FFMA2 inner loop.
// FROWS=16 (FROWS=32 spills acc[] -> +40us, established R5-R8)
#define FROWS 16
__global__ void k_final(const float* __restrict__ b2, float* __restrict__ out) {
    __shared__ float A[FROWS * DM];
    __shared__ float red[8];
    int c  = threadIdx.x;
    int j0 = blockIdx.x * FROWS;

#pragma unroll
    for (int r = 0; r < FROWS; r++)
        A[r * DM + c] = g_aggc[(j0 + r) * DM + c];
    __syncthreads();

    float bc = b2[c];
    unsigned long long acc2[FROWS];
    unsigned long long bcpk;
    asm("mov.b64 %0, {%1, %2};" : "=l"(bcpk) : "f"(bc), "f"(0.f));
#pragma unroll
    for (int r = 0; r < FROWS; r++) acc2[r] = bcpk;

    const ulonglong2* A8 = reinterpret_cast<const ulonglong2*>(A);  // {f0,f1},{f2,f3}
    const uint2* W2p2 = reinterpret_cast<const uint2*>(g_W2p);
#pragma unroll 4
    for (int kk = 0; kk < DM / 4; kk++) {
        uint2 wu = W2p2[kk * DM + c];               // 4 halves: k=4kk..4kk+3, col c
        float2 w01 = __half22float2(*reinterpret_cast<__half2*>(&wu.x));
        float2 w23 = __half22float2(*reinterpret_cast<__half2*>(&wu.y));
        unsigned long long wp01, wp23;
        asm("mov.b64 %0, {%1, %2};" : "=l"(wp01) : "f"(w01.x), "f"(w01.y));
        asm("mov.b64 %0, {%1, %2};" : "=l"(wp23) : "f"(w23.x), "f"(w23.y));
#pragma unroll
        for (int r = 0; r < FROWS; r++) {
            ulonglong2 av = A8[r * (DM / 4) + kk];  // LDS.128 broadcast
            asm("fma.rn.f32x2 %0, %1, %2, %0;" : "+l"(acc2[r]) : "l"(av.x), "l"(wp01));
            asm("fma.rn.f32x2 %0, %1, %2, %0;" : "+l"(acc2[r]) : "l"(av.y), "l"(wp23));
        }
    }

    float acc[FROWS];
#pragma unroll
    for (int r = 0; r < FROWS; r++) {
        float lo, hi;
        asm("mov.b64 {%0, %1}, %2;" : "=f"(lo), "=f"(hi) : "l"(acc2[r]));
        acc[r] = lo + hi;
    }

    int lane = c & 31, wid = c >> 5;
#pragma unroll 1
    for (int r = 0; r < FROWS; r++) {
        float v = acc[r];
#pragma unroll
        for (int o = 16; o; o >>= 1) v = fmaxf(v, __shfl_xor_sync(0xffffffffu, v, o));
        if (lane == 0) red[wid] = v;
        __syncthreads();
        float m = red[0];
#pragma unroll
        for (int w = 1; w < 8; w++) m = fmaxf(m, red[w]);
        __syncthreads();
        float s = __expf(acc[r] - m);
#pragma unroll
        for (int o = 16; o; o >>= 1) s += __shfl_xor_sync(0xffffffffu, s, o);
        if (lane == 0) red[wid] = s;
        __syncthreads();
        float tot = red[0];
#pragma unroll
        for (int w = 1; w < 8; w++) tot += red[w];
        __syncthreads();
        out[(j0 + r) * DM + c] = acc[r] - m - logf(tot);
    }
}

// ---------------- launch -----------------------------------------------------
extern "C" void kernel_launch(void* const* d_in, const int* in_sizes, int n_in,
                              void* d_out, int out_size) {
    const int*   x    = (const int*)d_in[0];   // (100000,1) int32
    const int*   ei   = (const int*)d_in[1];   // (2,800000) int32: [src | dst]
    const int*   mask = (const int*)d_in[2];   // (10000,)   int32
    const float* emb  = (const float*)d_in[3]; // (256,256)
    const float* W1   = (const float*)d_in[4]; // (256,256)
    const float* b1   = (const float*)d_in[5]; // (256,)
    const float* W2   = (const float*)d_in[6]; // (256,256)
    const float* b2   = (const float*)d_in[7]; // (256,)
    float* out = (float*)d_out;                // (10000,256)

    (void)in_sizes; (void)n_in; (void)out_size;

    k_init   <<<(NN + 255) / 256, 256>>>();
    k_degmark<<<(NE + NM + 255) / 256, 256>>>(ei, mask);
    k_scanEw <<<NSB + VC + NW2B, SB>>>(x, emb, W1, W2);  // scan+epilogue+EW+W2p
    k_place  <<<(NE + 255) / 256, 256>>>(ei);
    k_gather1<<<(NN + 3) / 4, 256>>>(x, b1);
    k_gather2<<<(NM * 64 + 255) / 256, 256>>>(mask);
    k_final  <<<NM / FROWS, DM>>>(b2, out);
}

// round 17
// speedup vs baseline: 1.0428x; 1.0084x over previous
#include <cuda_runtime.h>
#include <cuda_fp16.h>

// Problem constants (fixed shapes for this problem instance)
#define NN 100000   // nodes
#define NE 800000   // edges
#define VC 256      // vocab
#define DM 256      // node dim == hidden == vocab
#define NM 10000    // masked outputs

#define SB 512
#define NSB ((NN + SB - 1) / SB)   // 196 scan blocks
#define NW2B 128                   // W2 cvt blocks (65536 elems / 512)

// ---------------- scratch (device globals; no allocation allowed) ----------
__device__ int   g_deg[NN];
__device__ int   g_cur[NN];     // seeded to off | masked<<31 in scan epilogue
__device__ int   g_off[NN];
__device__ int   g_masked[NN];
__device__ int   g_needed[NN];
__device__ float g_dinv[NN];
__device__ unsigned long long g_state[NSB];        // lookback: flag<<62 | value
__device__ __align__(8)  int2   g_nv[NN];          // {x, dinv_bits}
__device__ __align__(16) __half g_EWh[VC * DM];    // emb @ W1, fp16 (128 KB)
__device__ __align__(16) __half g_W2p[DM * VC];    // W2 fp16, k-quad packed (128 KB)
__device__ __align__(16) __half g_out1h[NN * DM];  // relu(layer-1), fp16 (51 MB)
__device__ __align__(16) float  g_aggc[NM * DM];   // layer-2 aggregate (10 MB)
__device__ __align__(16) int4   g_edge[NE];        // {x[src], src, dinv_s_bits, 0}

// ---------------- kernels ---------------------------------------------------
__global__ void k_init(void) {
    int i = blockIdx.x * blockDim.x + threadIdx.x;
    if (i < NN) { g_deg[i] = 1; g_masked[i] = 0; g_needed[i] = 0; }
    if (i < NSB) g_state[i] = 0ULL;                 // reset lookback states
}

// degree count (first NE threads) + mask marking (next NM)
__global__ void k_degmark(const int* __restrict__ ei, const int* __restrict__ mask) {
    int t = blockIdx.x * blockDim.x + threadIdx.x;
    if (t < NE) {
        atomicAdd(&g_deg[ei[NE + t]], 1);
    } else if (t < NE + NM) {
        int n = mask[t - NE];
        g_masked[n] = 1;
        g_needed[n] = 1;          // self term of layer-2 reads out1[node]
    }
}

// ONE kernel: blocks [0,NSB) = single-pass scan of (deg-1) with WARP-PARALLEL
// decoupled lookback + full epilogue (off, cur|masked<<31, dinv, nv).
// Blocks [NSB,NSB+VC) = EW rows. Blocks [NSB+VC,+NW2B) = W2 fp16 k-quad pack.
// Deadlock-safe: scan blocks are bids 0..195, all wave-1 co-resident.
__global__ void __launch_bounds__(SB) k_scanEw(const int* __restrict__ x,
                                               const float* __restrict__ emb,
                                               const float* __restrict__ W1,
                                               const float* __restrict__ W2) {
    __shared__ float sf[SB];
    __shared__ unsigned sh_excl;
    if (blockIdx.x < NSB) {
        // ---- per-block inclusive scan of (deg-1) ----
        int* s = reinterpret_cast<int*>(sf);
        int i = blockIdx.x * SB + threadIdx.x;
        int v = (i < NN) ? (g_deg[i] - 1) : 0;
        s[threadIdx.x] = v;
        __syncthreads();
        for (int o = 1; o < SB; o <<= 1) {
            int t = (threadIdx.x >= o) ? s[threadIdx.x - o] : 0;
            __syncthreads();
            s[threadIdx.x] += t;
            __syncthreads();
        }
        int inc = s[threadIdx.x];
        int blockAgg = s[SB - 1];

        // ---- warp-parallel decoupled lookback (warp 0) ----
        // Lanes read 32 predecessor states per round (1 parallel L2 round-trip
        // instead of 32 serial ones); ballot finds the flag-2 frontier.
        if (threadIdx.x < 32) {
            int lane = threadIdx.x;
            unsigned excl = 0;
            if (blockIdx.x == 0) {
                if (lane == 0)
                    atomicExch(&g_state[0], (2ULL << 62) | (unsigned)blockAgg);
            } else {
                if (lane == 0)
                    atomicExch(&g_state[blockIdx.x], (1ULL << 62) | (unsigned)blockAgg);
                int base = blockIdx.x - 1;
                while (true) {
                    int idx = base - lane;
                    unsigned long long st = (idx >= 0)
                        ? atomicAdd(&g_state[idx], 0ULL)
                        : (2ULL << 62);             // before block 0: prefix 0
                    unsigned f = (unsigned)(st >> 62);
                    unsigned zero_mask = __ballot_sync(0xffffffffu, f == 0u);
                    unsigned two_mask  = __ballot_sync(0xffffffffu, f == 2u);
                    int firstTwo  = two_mask  ? (__ffs(two_mask) - 1)  : 32;
                    int firstZero = zero_mask ? (__ffs(zero_mask) - 1) : 32;
                    if (firstZero < firstTwo) continue;   // gap: retry window
                    unsigned contrib = (lane <= firstTwo) ? (unsigned)(st & 0xFFFFFFFFu) : 0u;
#pragma unroll
                    for (int o = 16; o; o >>= 1)
                        contrib += __shfl_xor_sync(0xffffffffu, contrib, o);
                    excl += contrib;
                    if (firstTwo < 32) break;       // hit an inclusive prefix
                    base -= 32;
                }
                if (lane == 0)
                    atomicExch(&g_state[blockIdx.x],
                               (2ULL << 62) | (unsigned long long)(excl + (unsigned)blockAgg));
            }
            if (lane == 0) sh_excl = excl;
        }
        __syncthreads();

        // ---- epilogue: offsets, cur|flag, dinv, node record ----
        if (i < NN) {
            int off = (inc - v) + (int)sh_excl;     // exclusive global prefix
            g_off[i] = off;
            g_cur[i] = off | (g_masked[i] << 31);   // atomic return carries flag
            float di = rsqrtf((float)(v + 1));      // deg = v+1 (self loop incl)
            g_dinv[i] = di;
            g_nv[i] = make_int2(x[i], __float_as_int(di));
        }
    } else if (blockIdx.x < NSB + VC) {
        // ---- EW row: g_EWh[r] = fp16(emb[r] @ W1) ----
        int r = blockIdx.x - NSB;
        int c = threadIdx.x;
        if (c < DM) sf[c] = emb[r * DM + c];
        __syncthreads();
        if (c >= DM) return;
        float acc = 0.f;
#pragma unroll 8
        for (int k = 0; k < DM; k++) acc += sf[k] * W1[k * DM + c];
        g_EWh[r * DM + c] = __float2half(acc);
    } else {
        // ---- W2 cvt + k-quad pack: W2p[(kk*256+c)*4+i] = fp16(W2[(4kk+i)*256+c])
        int o = (blockIdx.x - NSB - VC) * SB + threadIdx.x;   // 0..65535
        int i = o & 3;
        int c = (o >> 2) & (DM - 1);
        int kk = o >> 10;
        g_W2p[o] = __float2half(W2[(4 * kk + i) * DM + c]);
    }
}

// place edges into CSR slots. 3 scattered ops/edge: nv[s] read, atomic
// (slot + masked flag in bit31), 16B record store (int4 -> decode-free gathers).
__global__ void k_place(const int* __restrict__ ei) {
    int e = blockIdx.x * blockDim.x + threadIdx.x;
    if (e >= NE) return;
    int s = ei[e];
    int d = ei[NE + e];
    int2 nvs = g_nv[s];                             // {x[s], dinv_s}
    int old = atomicAdd(&g_cur[d], 1);
    int slot = old & 0x7fffffff;
    g_edge[slot] = make_int4(nvs.x, s, nvs.y, 0);
    if (old < 0) g_needed[s] = 1;                   // dst is masked
}

// layer-1 gather: out1h[i] = fp16(relu(b1 + di*(di*EW[x[i]] + sum ds*EW[x_s])))
// 64 threads/node; EW fp16 (L1-resident); R11/R14-proven inner loop shape.
__global__ void k_gather1(const int* __restrict__ x, const float* __restrict__ b1) {
    int node = blockIdx.x * 4 + (threadIdx.x >> 6);
    if (node >= NN) return;
    if (!g_needed[node]) return;                    // uniform per 64-thread group
    int q = threadIdx.x & 63;

    const uint2* EW2 = reinterpret_cast<const uint2*>(g_EWh);  // 4 halves/thread
    float di = g_dinv[node];

    uint2 w0u = EW2[x[node] * 64 + q];
    float2 f0a = __half22float2(*reinterpret_cast<__half2*>(&w0u.x));
    float2 f0b = __half22float2(*reinterpret_cast<__half2*>(&w0u.y));
    float4 acc = make_float4(di * f0a.x, di * f0a.y, di * f0b.x, di * f0b.y);

    int k   = g_off[node];
    int end = k + g_deg[node] - 1;
    for (; k < end; k++) {
        int4 rec = g_edge[k];                       // broadcast LDG.128
        float ds = __int_as_float(rec.z);
        uint2 wu = EW2[rec.x * 64 + q];             // L1 hit (128 KB working set)
        float2 fa = __half22float2(*reinterpret_cast<__half2*>(&wu.x));
        float2 fb = __half22float2(*reinterpret_cast<__half2*>(&wu.y));
        acc.x += ds * fa.x; acc.y += ds * fa.y;
        acc.z += ds * fb.x; acc.w += ds * fb.y;
    }
    float4 bb = reinterpret_cast<const float4*>(b1)[q];
    float4 res = make_float4(bb.x + di * acc.x, bb.y + di * acc.y,
                             bb.z + di * acc.z, bb.w + di * acc.w);

    // store relu(res) fp16 — layer 2 only ever consumes relu(out1)
    __half2 oa = __floats2half2_rn(fmaxf(res.x, 0.f), fmaxf(res.y, 0.f));
    __half2 ob = __floats2half2_rn(fmaxf(res.z, 0.f), fmaxf(res.w, 0.f));
    uint2 ou;
    ou.x = *reinterpret_cast<unsigned*>(&oa);
    ou.y = *reinterpret_cast<unsigned*>(&ob);
    reinterpret_cast<uint2*>(g_out1h)[node * 64 + q] = ou;
}

// layer-2 gather, masked entries only (compact j-indexed output):
//   aggc[j] = di*(di*h1[node] + sum ds*h1[src])   (h1 already relu'd)
__global__ void k_gather2(const int* __restrict__ mask) {
    int gid = blockIdx.x * blockDim.x + threadIdx.x;
    int j = gid >> 6;
    if (j >= NM) return;
    int q = gid & 63;
    int node = mask[j];

    const uint2* O2 = reinterpret_cast<const uint2*>(g_out1h);
    float di = g_dinv[node];

    uint2 hu = O2[node * 64 + q];
    float2 ha = __half22float2(*reinterpret_cast<__half2*>(&hu.x));
    float2 hb = __half22float2(*reinterpret_cast<__half2*>(&hu.y));
    float4 acc = make_float4(di * ha.x, di * ha.y, di * hb.x, di * hb.y);

    int k   = g_off[node];
    int end = k + g_deg[node] - 1;
    for (; k < end; k++) {
        int4 rec = g_edge[k];                       // broadcast LDG.128
        float ds = __int_as_float(rec.z);
        uint2 su = O2[rec.y * 64 + q];              // 512B scattered row
        float2 sa = __half22float2(*reinterpret_cast<__half2*>(&su.x));
        float2 sb = __half22float2(*reinterpret_cast<__half2*>(&su.y));
        acc.x += ds * sa.x; acc.y += ds * sa.y;
        acc.z += ds * sb.x; acc.w += ds * sb.y;
    }
    reinterpret_cast<float4*>(g_aggc)[j * 64 + q] =
        make_float4(di * acc.x, di * acc.y, di * acc.z, di * acc.w);
}

// out[j] = log_softmax(aggc[j] @ W2 + b2); W2 fp16 k-quad packed, FFMA2 inner loop.
// FROWS=16 (FROWS=32 spills acc[] -> +40us, established R5-R8)
#define FROWS 16
__global__ void k_final(const float* __restrict__ b2, float* __restrict__ out) {
    __shared__ float A[FROWS * DM];
    __shared__ float red[8];
    int c  = threadIdx.x;
    int j0 = blockIdx.x * FROWS;

#pragma unroll
    for (int r = 0; r < FROWS; r++)
        A[r * DM + c] = g_aggc[(j0 + r) * DM + c];
    __syncthreads();

    float bc = b2[c];
    unsigned long long acc2[FROWS];
    unsigned long long bcpk;
    asm("mov.b64 %0, {%1, %2};" : "=l"(bcpk) : "f"(bc), "f"(0.f));
#pragma unroll
    for (int r = 0; r < FROWS; r++) acc2[r] = bcpk;

    const ulonglong2* A8 = reinterpret_cast<const ulonglong2*>(A);  // {f0,f1},{f2,f3}
    const uint2* W2p2 = reinterpret_cast<const uint2*>(g_W2p);
#pragma unroll 4
    for (int kk = 0; kk < DM / 4; kk++) {
        uint2 wu = W2p2[kk * DM + c];               // 4 halves: k=4kk..4kk+3, col c
        float2 w01 = __half22float2(*reinterpret_cast<__half2*>(&wu.x));
        float2 w23 = __half22float2(*reinterpret_cast<__half2*>(&wu.y));
        unsigned long long wp01, wp23;
        asm("mov.b64 %0, {%1, %2};" : "=l"(wp01) : "f"(w01.x), "f"(w01.y));
        asm("mov.b64 %0, {%1, %2};" : "=l"(wp23) : "f"(w23.x), "f"(w23.y));
#pragma unroll
        for (int r = 0; r < FROWS; r++) {
            ulonglong2 av = A8[r * (DM / 4) + kk];  // LDS.128 broadcast
            asm("fma.rn.f32x2 %0, %1, %2, %0;" : "+l"(acc2[r]) : "l"(av.x), "l"(wp01));
            asm("fma.rn.f32x2 %0, %1, %2, %0;" : "+l"(acc2[r]) : "l"(av.y), "l"(wp23));
        }
    }

    float acc[FROWS];
#pragma unroll
    for (int r = 0; r < FROWS; r++) {
        float lo, hi;
        asm("mov.b64 {%0, %1}, %2;" : "=f"(lo), "=f"(hi) : "l"(acc2[r]));
        acc[r] = lo + hi;
    }

    int lane = c & 31, wid = c >> 5;
#pragma unroll 1
    for (int r = 0; r < FROWS; r++) {
        float v = acc[r];
#pragma unroll
        for (int o = 16; o; o >>= 1) v = fmaxf(v, __shfl_xor_sync(0xffffffffu, v, o));
        if (lane == 0) red[wid] = v;
        __syncthreads();
        float m = red[0];
#pragma unroll
        for (int w = 1; w < 8; w++) m = fmaxf(m, red[w]);
        __syncthreads();
        float s = __expf(acc[r] - m);
#pragma unroll
        for (int o = 16; o; o >>= 1) s += __shfl_xor_sync(0xffffffffu, s, o);
        if (lane == 0) red[wid] = s;
        __syncthreads();
        float tot = red[0];
#pragma unroll
        for (int w = 1; w < 8; w++) tot += red[w];
        __syncthreads();
        out[(j0 + r) * DM + c] = acc[r] - m - logf(tot);
    }
}

// ---------------- launch -----------------------------------------------------
extern "C" void kernel_launch(void* const* d_in, const int* in_sizes, int n_in,
                              void* d_out, int out_size) {
    const int*   x    = (const int*)d_in[0];   // (100000,1) int32
    const int*   ei   = (const int*)d_in[1];   // (2,800000) int32: [src | dst]
    const int*   mask = (const int*)d_in[2];   // (10000,)   int32
    const float* emb  = (const float*)d_in[3]; // (256,256)
    const float* W1   = (const float*)d_in[4]; // (256,256)
    const float* b1   = (const float*)d_in[5]; // (256,)
    const float* W2   = (const float*)d_in[6]; // (256,256)
    const float* b2   = (const float*)d_in[7]; // (256,)
    float* out = (float*)d_out;                // (10000,256)

    (void)in_sizes; (void)n_in; (void)out_size;

    k_init   <<<(NN + 255) / 256, 256>>>();
    k_degmark<<<(NE + NM + 255) / 256, 256>>>(ei, mask);
    k_scanEw <<<NSB + VC + NW2B, SB>>>(x, emb, W1, W2);  // scan+epilogue+EW+W2p
    k_place  <<<(NE + 255) / 256, 256>>>(ei);
    k_gather1<<<(NN + 3) / 4, 256>>>(x, b1);
    k_gather2<<<(NM * 64 + 255) / 256, 256>>>(mask);
    k_final  <<<NM / FROWS, DM>>>(b2, out);
}